// round 15
// baseline (speedup 1.0000x reference)
#include <cuda_runtime.h>
#include <cuda_bf16.h>
#include <math.h>

#define E       1024
#define DH      64
#define NF      80
#define MT      128
#define KB      32          // k-chunk staged per iteration
#define NCHUNK  (E / KB)    // 32
#define NROWS   32768
#define NTILES  256
#define NBATCH  4

// smem: GEMM staging (row stride 80B, conflict-free for fragment LDS) overlaid with sP
#define RS      80          // padded row stride in bytes (16B-aligned, bank-clean)
#define AH_OFF  0           // x hi   [128][RS]
#define AL_OFF  10240       // x lo   [128][RS]
#define BH_OFF  20480       // W hi   [80][RS]
#define BL_OFF  26880       // W lo   [80][RS]
#define SMEM_BYTES 44032    // >= max(33280 staging, 43008 sP)

typedef unsigned int u32;

__device__ __align__(16) __nv_bfloat16 g_Whi[NF * E];
__device__ __align__(16) __nv_bfloat16 g_Wlo[NF * E];
__device__ float g_call[NF];
__device__ float g_qP[NROWS * 16];
__device__ float g_Spart[NTILES * 1024];
__device__ float g_S[NBATCH * 1024];

__device__ __forceinline__ void mma_bf16(float& c0, float& c1, float& c2, float& c3,
                                         u32 a0, u32 a1, u32 a2, u32 a3,
                                         u32 b0, u32 b1) {
    asm volatile(
        "mma.sync.aligned.m16n8k16.row.col.f32.bf16.bf16.f32 "
        "{%0,%1,%2,%3}, {%4,%5,%6,%7}, {%8,%9}, {%0,%1,%2,%3};"
        : "+f"(c0), "+f"(c1), "+f"(c2), "+f"(c3)
        : "r"(a0), "r"(a1), "r"(a2), "r"(a3), "r"(b0), "r"(b1));
}

// ---------------- kernel 1: fold weights to bf16 hi/lo, K-major [n][k] ----
__global__ void prep_kernel(const float* __restrict__ w,
                            const float* __restrict__ Wq, const float* __restrict__ bq,
                            const float* __restrict__ Wk, const float* __restrict__ bk,
                            const float* __restrict__ Wv, const float* __restrict__ bv) {
    int n = blockIdx.x;       // 0..79
    int tid = threadIdx.x;    // 128
    for (int k = tid * 8; k < tid * 8 + 8; k++) {
        float a;
        if (n < 8) {
            a = 0.f;
            #pragma unroll 8
            for (int d = 0; d < DH; d++) a += Wq[k * DH + d] * w[d * 8 + n];
        } else if (n < 16) {
            a = 0.f;
            #pragma unroll 8
            for (int d = 0; d < DH; d++) a += Wk[k * DH + d] * w[d * 8 + (n - 8)];
        } else {
            a = Wv[k * DH + (n - 16)];
        }
        __nv_bfloat16 hi = __float2bfloat16_rn(a);
        float lf = a - __bfloat162float(hi);
        g_Whi[n * E + k] = hi;
        g_Wlo[n * E + k] = __float2bfloat16_rn(lf);
    }
    if (tid == 0) {
        float c;
        if (n < 8)       { c = 0.f; for (int d = 0; d < DH; d++) c += bq[d] * w[d * 8 + n]; }
        else if (n < 16) { c = 0.f; for (int d = 0; d < DH; d++) c += bk[d] * w[d * 8 + (n - 8)]; }
        else c = bv[n - 16];
        g_call[n] = c;
    }
}

// ---------------- kernel 2: mma.sync split-bf16 GEMM + epilogue ----------
__global__ __launch_bounds__(128) void favor_main(const float* __restrict__ x) {
    static __shared__ __align__(16) unsigned char smem[SMEM_BYTES];

    const int tid   = threadIdx.x;
    const int wid   = tid >> 5;
    const int lane  = tid & 31;
    const int g     = lane >> 2;     // groupID 0..7
    const int t     = lane & 3;      // thread-in-group 0..3
    const int wbase = wid * 32;      // warp's M offset in tile
    const int row0  = blockIdx.x * MT;

    float acc[2][10][4];
    #pragma unroll
    for (int mt = 0; mt < 2; mt++)
        #pragma unroll
        for (int nt = 0; nt < 10; nt++)
            #pragma unroll
            for (int i = 0; i < 4; i++) acc[mt][nt][i] = 0.f;

    #pragma unroll 1
    for (int c = 0; c < NCHUNK; c++) {
        const int kt = c * KB;

        // ---- stage x chunk [128][32] fp32 -> hi/lo bf16
        #pragma unroll
        for (int i = 0; i < 4; i++) {
            int u   = i * 128 + tid;      // 0..511 units of 8 floats
            int row = u >> 2;
            int seg = u & 3;
            const float* gp = x + (size_t)(row0 + row) * E + kt + seg * 8;
            float4 va = *reinterpret_cast<const float4*>(gp);
            float4 vb = *reinterpret_cast<const float4*>(gp + 4);
            float v[8] = {va.x, va.y, va.z, va.w, vb.x, vb.y, vb.z, vb.w};
            u32 h[4], l[4];
            #pragma unroll
            for (int j = 0; j < 4; j++) {
                __nv_bfloat162 hv = __floats2bfloat162_rn(v[2*j], v[2*j+1]);
                float l0 = v[2*j]   - __bfloat162float(__low2bfloat16(hv));
                float l1 = v[2*j+1] - __bfloat162float(__high2bfloat16(hv));
                __nv_bfloat162 lv = __floats2bfloat162_rn(l0, l1);
                h[j] = *reinterpret_cast<u32*>(&hv);
                l[j] = *reinterpret_cast<u32*>(&lv);
            }
            *reinterpret_cast<uint4*>(smem + AH_OFF + row * RS + seg * 16) = make_uint4(h[0], h[1], h[2], h[3]);
            *reinterpret_cast<uint4*>(smem + AL_OFF + row * RS + seg * 16) = make_uint4(l[0], l[1], l[2], l[3]);
        }
        // ---- stage W chunk [80][32] bf16 hi+lo (640 16B units)
        #pragma unroll
        for (int i = 0; i < 5; i++) {
            int idx = i * 128 + tid;      // 0..639
            int m   = idx >= 320;
            int r   = idx - m * 320;
            int n   = r >> 2;
            int seg = r & 3;
            const __nv_bfloat16* src = m ? g_Wlo : g_Whi;
            uint4 v = *reinterpret_cast<const uint4*>(src + (size_t)n * E + kt + seg * 8);
            *reinterpret_cast<uint4*>(smem + (m ? BL_OFF : BH_OFF) + n * RS + seg * 16) = v;
        }
        __syncthreads();

        // ---- compute: 2 k16 steps
        #pragma unroll
        for (int s = 0; s < 2; s++) {
            const int koff = 4 * t + 32 * s;   // byte offset of this lane's k-pair
            u32 ah[2][4], al[2][4];
            #pragma unroll
            for (int mt = 0; mt < 2; mt++) {
                const unsigned char* pH = smem + AH_OFF + (wbase + 16 * mt + g) * RS + koff;
                const unsigned char* pL = smem + AL_OFF + (wbase + 16 * mt + g) * RS + koff;
                ah[mt][0] = *reinterpret_cast<const u32*>(pH);
                ah[mt][1] = *reinterpret_cast<const u32*>(pH + 8 * RS);
                ah[mt][2] = *reinterpret_cast<const u32*>(pH + 16);
                ah[mt][3] = *reinterpret_cast<const u32*>(pH + 8 * RS + 16);
                al[mt][0] = *reinterpret_cast<const u32*>(pL);
                al[mt][1] = *reinterpret_cast<const u32*>(pL + 8 * RS);
                al[mt][2] = *reinterpret_cast<const u32*>(pL + 16);
                al[mt][3] = *reinterpret_cast<const u32*>(pL + 8 * RS + 16);
            }
            #pragma unroll
            for (int nt = 0; nt < 10; nt++) {
                const unsigned char* pBH = smem + BH_OFF + (8 * nt + g) * RS + koff;
                const unsigned char* pBL = smem + BL_OFF + (8 * nt + g) * RS + koff;
                u32 bh0 = *reinterpret_cast<const u32*>(pBH);
                u32 bh1 = *reinterpret_cast<const u32*>(pBH + 16);
                u32 bl0 = *reinterpret_cast<const u32*>(pBL);
                u32 bl1 = *reinterpret_cast<const u32*>(pBL + 16);
                #pragma unroll
                for (int mt = 0; mt < 2; mt++) {
                    float* cc = acc[mt][nt];
                    mma_bf16(cc[0], cc[1], cc[2], cc[3],
                             ah[mt][0], ah[mt][1], ah[mt][2], ah[mt][3], bh0, bh1);
                    mma_bf16(cc[0], cc[1], cc[2], cc[3],
                             ah[mt][0], ah[mt][1], ah[mt][2], ah[mt][3], bl0, bl1);
                    mma_bf16(cc[0], cc[1], cc[2], cc[3],
                             al[mt][0], al[mt][1], al[mt][2], al[mt][3], bh0, bh1);
                }
            }
        }
        __syncthreads();
    }

    // ---- stage P = acc + bias into sP overlay
    float (*sP)[84] = reinterpret_cast<float(*)[84]>(smem);
    #pragma unroll
    for (int mt = 0; mt < 2; mt++) {
        int r = wbase + 16 * mt + g;
        #pragma unroll
        for (int nt = 0; nt < 10; nt++) {
            int col = 8 * nt + 2 * t;
            float b0 = g_call[col], b1 = g_call[col + 1];
            sP[r][col]       = acc[mt][nt][0] + b0;
            sP[r][col + 1]   = acc[mt][nt][1] + b1;
            sP[r + 8][col]     = acc[mt][nt][2] + b0;
            sP[r + 8][col + 1] = acc[mt][nt][3] + b1;
        }
    }
    __syncthreads();

    // ---- feature maps: one row per thread
    {
        const float INV = 0.3535533905932738f;  // 1/sqrt(8)
        float qs[8], qc[8], ks[8], kc[8];
        #pragma unroll
        for (int f = 0; f < 8; f++) sincosf(sP[tid][f],     &qs[f], &qc[f]);
        #pragma unroll
        for (int f = 0; f < 8; f++) sincosf(sP[tid][8 + f], &ks[f], &kc[f]);
        float4* gq = reinterpret_cast<float4*>(&g_qP[(size_t)(row0 + tid) * 16]);
        gq[0] = make_float4(qc[0]*INV, qc[1]*INV, qc[2]*INV, qc[3]*INV);
        gq[1] = make_float4(qc[4]*INV, qc[5]*INV, qc[6]*INV, qc[7]*INV);
        gq[2] = make_float4(qs[0]*INV, qs[1]*INV, qs[2]*INV, qs[3]*INV);
        gq[3] = make_float4(qs[4]*INV, qs[5]*INV, qs[6]*INV, qs[7]*INV);
        #pragma unroll
        for (int f = 0; f < 8; f++) { sP[tid][f] = kc[f]*INV; sP[tid][8 + f] = ks[f]*INV; }
    }
    __syncthreads();

    // ---- per-CTA partial S[16][64]
    {
        int f  = tid >> 3;
        int dd = (tid & 7) * 8;
        float s[8];
        #pragma unroll
        for (int j = 0; j < 8; j++) s[j] = 0.f;
        for (int r = 0; r < MT; r++) {
            float  kp = sP[r][f];
            float4 v0 = *reinterpret_cast<const float4*>(&sP[r][16 + dd]);
            float4 v1 = *reinterpret_cast<const float4*>(&sP[r][16 + dd + 4]);
            s[0] += kp * v0.x; s[1] += kp * v0.y; s[2] += kp * v0.z; s[3] += kp * v0.w;
            s[4] += kp * v1.x; s[5] += kp * v1.y; s[6] += kp * v1.z; s[7] += kp * v1.w;
        }
        float* dst = &g_Spart[(size_t)blockIdx.x * 1024 + f * 64 + dd];
        #pragma unroll
        for (int j = 0; j < 8; j++) dst[j] = s[j];
    }
}

// ---------------- kernel 3: reduce partial S --------------------------
__global__ void reduce_S_kernel() {
    int idx = blockIdx.x * 256 + threadIdx.x;
    int bi  = idx >> 10;
    int e   = idx & 1023;
    float s = 0.f;
    const float* src = &g_Spart[(size_t)bi * 64 * 1024 + e];
    #pragma unroll 8
    for (int j = 0; j < 64; j++) s += src[j * 1024];
    g_S[idx] = s;
}

// ---------------- kernel 4: y = qP @ S (half-row per thread) -----------
__global__ __launch_bounds__(128) void final_kernel(float* __restrict__ out) {
    __shared__ float4 sS[256];
    int tid  = threadIdx.x;
    int row  = blockIdx.x * 64 + (tid >> 1);
    int half = tid & 1;
    int bi   = row >> 13;
    sS[tid]       = reinterpret_cast<const float4*>(&g_S[bi * 1024])[tid];
    sS[tid + 128] = reinterpret_cast<const float4*>(&g_S[bi * 1024])[tid + 128];
    __syncthreads();

    float qf[16];
    const float4* qp4 = reinterpret_cast<const float4*>(&g_qP[(size_t)row * 16]);
    #pragma unroll
    for (int i = 0; i < 4; i++) {
        float4 q = qp4[i];
        qf[i*4] = q.x; qf[i*4+1] = q.y; qf[i*4+2] = q.z; qf[i*4+3] = q.w;
    }
    float4 o[8];
    #pragma unroll
    for (int d = 0; d < 8; d++) o[d] = make_float4(0.f, 0.f, 0.f, 0.f);
    #pragma unroll
    for (int f = 0; f < 16; f++) {
        float q = qf[f];
        #pragma unroll
        for (int d = 0; d < 8; d++) {
            float4 sv = sS[f * 16 + half * 8 + d];
            o[d].x += q * sv.x; o[d].y += q * sv.y; o[d].z += q * sv.z; o[d].w += q * sv.w;
        }
    }
    float4* po = reinterpret_cast<float4*>(out + (size_t)row * 64);
    #pragma unroll
    for (int d = 0; d < 8; d++) po[half * 8 + d] = o[d];
}

// ---------------- launch -----------------------------------------------
extern "C" void kernel_launch(void* const* d_in, const int* in_sizes, int n_in,
                              void* d_out, int out_size) {
    const float* x  = (const float*)d_in[0];
    const float* w  = (const float*)d_in[1];
    const float* Wq = (const float*)d_in[2];
    const float* bq = (const float*)d_in[3];
    const float* Wk = (const float*)d_in[4];
    const float* bk = (const float*)d_in[5];
    const float* Wv = (const float*)d_in[6];
    const float* bv = (const float*)d_in[7];
    float* out = (float*)d_out;

    prep_kernel<<<NF, 128>>>(w, Wq, bq, Wk, bk, Wv, bv);
    favor_main<<<NTILES, 128>>>(x);
    reduce_S_kernel<<<16, 256>>>();
    final_kernel<<<512, 128>>>(out);
}